// round 1
// baseline (speedup 1.0000x reference)
#include <cuda_runtime.h>
#include <cstdint>
#include <cstddef>

// Problem dims
#define BROWS 4096
#define NB1   128   // stage-1 blocks (n)
#define I1    64    // inputs per block 1 (k of stage 1)
#define MMID  64    // mid dim (m) = outputs per block 1 = n_blocks_2
#define O2    128   // outputs per block 2 (o)

// Scratch: t layout [b][m][n]  (n contiguous) -> stage-2 rows are contiguous
__device__ float g_t[(size_t)BROWS * MMID * NB1];          // 128 MB
__device__ float g_w1[NB1 * I1 * MMID];                    // softmaxed, tf32-rounded, [n][i][m]
__device__ float g_w2[MMID * NB1 * O2];                    // softmaxed, tf32-rounded, [m][n][o]

__device__ __forceinline__ float f2tf_f(float f) {
    unsigned u;
    asm("cvt.rna.tf32.f32 %0, %1;" : "=r"(u) : "f"(f));
    return __uint_as_float(u);
}

__device__ __forceinline__ void mma_tf32(float& d0, float& d1, float& d2, float& d3,
                                         unsigned a0, unsigned a1, unsigned a2, unsigned a3,
                                         unsigned b0, unsigned b1) {
    asm volatile(
        "mma.sync.aligned.m16n8k8.row.col.f32.tf32.tf32.f32 "
        "{%0,%1,%2,%3}, {%4,%5,%6,%7}, {%8,%9}, {%0,%1,%2,%3};"
        : "+f"(d0), "+f"(d1), "+f"(d2), "+f"(d3)
        : "r"(a0), "r"(a1), "r"(a2), "r"(a3), "r"(b0), "r"(b1));
}

// ---------------- softmax precompute ----------------
// w1[n,i,m] = softmax over i of 3*c1[n,i,m]
__global__ void softmax1_kernel(const float* __restrict__ c1) {
    int n = blockIdx.x;          // 128
    int m = threadIdx.x;         // 64
    const float* col = c1 + (size_t)n * I1 * MMID + m;
    float v[I1];
    float mx = -1e30f;
#pragma unroll
    for (int i = 0; i < I1; i++) { v[i] = col[i * MMID] * 3.0f; mx = fmaxf(mx, v[i]); }
    float s = 0.0f;
#pragma unroll
    for (int i = 0; i < I1; i++) { v[i] = expf(v[i] - mx); s += v[i]; }
    float inv = 1.0f / s;
    float* out = g_w1 + (size_t)n * I1 * MMID + m;
#pragma unroll
    for (int i = 0; i < I1; i++) out[i * MMID] = f2tf_f(v[i] * inv);
}

// w2[m,n,o] = softmax over n of 3*c2[m,n,o]
__global__ void softmax2_kernel(const float* __restrict__ c2) {
    int m = blockIdx.x;          // 64
    int o = threadIdx.x;         // 128
    const float* col = c2 + (size_t)m * NB1 * O2 + o;
    float mx = -1e30f;
    for (int n = 0; n < NB1; n++) mx = fmaxf(mx, col[n * O2] * 3.0f);
    float s = 0.0f;
    for (int n = 0; n < NB1; n++) s += expf(col[n * O2] * 3.0f - mx);
    float inv = 1.0f / s;
    float* out = g_w2 + (size_t)m * NB1 * O2 + o;
    for (int n = 0; n < NB1; n++) out[n * O2] = f2tf_f(expf(col[n * O2] * 3.0f - mx) * inv);
}

// ---------------- stage 1 ----------------
// CTA: 64 batch rows x 8 n-blocks. 256 thr = 8 warps, warp grid 4(row)x2(col),
// warp tile 16x32. Accumulators for all 8 n-slices kept in registers,
// flushed as 32B-aligned float4 pairs into t[b][m][n].
#define S1P 68
__global__ __launch_bounds__(256, 1) void stage1_kernel(const float* __restrict__ x) {
    __shared__ float xs[64 * S1P];
    __shared__ float ws[64 * S1P];
    int b0  = blockIdx.x * 64;
    int ng0 = blockIdx.y * 8;
    int tid = threadIdx.x;
    int wid = tid >> 5, lane = tid & 31, g = lane >> 2, tg = lane & 3;
    int wrow = (wid & 3) * 16;
    int wcol = (wid >> 2) * 32;

    float acc[8][4][4];
#pragma unroll
    for (int a = 0; a < 8; a++)
#pragma unroll
        for (int b = 0; b < 4; b++)
#pragma unroll
            for (int c = 0; c < 4; c++) acc[a][b][c] = 0.0f;

#pragma unroll
    for (int nn = 0; nn < 8; nn++) {
        int n = ng0 + nn;
        __syncthreads();
        // load x tile (tf32-round), 64x64
        for (int idx = tid; idx < 1024; idx += 256) {
            int r = idx >> 4, c = idx & 15;
            float4 v = *(const float4*)(x + (size_t)(b0 + r) * 8192 + (size_t)n * 64 + c * 4);
            float* p = xs + r * S1P + c * 4;
            p[0] = f2tf_f(v.x); p[1] = f2tf_f(v.y); p[2] = f2tf_f(v.z); p[3] = f2tf_f(v.w);
        }
        // load w1[n] (already rounded)
        for (int idx = tid; idx < 1024; idx += 256) {
            int r = idx >> 4, c = idx & 15;
            float4 v = *(const float4*)(g_w1 + ((size_t)n * 64 + r) * 64 + c * 4);
            float* p = ws + r * S1P + c * 4;
            p[0] = v.x; p[1] = v.y; p[2] = v.z; p[3] = v.w;
        }
        __syncthreads();
#pragma unroll
        for (int kk = 0; kk < 8; kk++) {
            int k0 = kk * 8;
            unsigned a0 = __float_as_uint(xs[(wrow + g) * S1P + k0 + tg]);
            unsigned a1 = __float_as_uint(xs[(wrow + g + 8) * S1P + k0 + tg]);
            unsigned a2 = __float_as_uint(xs[(wrow + g) * S1P + k0 + tg + 4]);
            unsigned a3 = __float_as_uint(xs[(wrow + g + 8) * S1P + k0 + tg + 4]);
#pragma unroll
            for (int nt = 0; nt < 4; nt++) {
                int col = wcol + nt * 8 + g;
                unsigned b0r = __float_as_uint(ws[(k0 + tg) * S1P + col]);
                unsigned b1r = __float_as_uint(ws[(k0 + tg + 4) * S1P + col]);
                mma_tf32(acc[nn][nt][0], acc[nn][nt][1], acc[nn][nt][2], acc[nn][nt][3],
                         a0, a1, a2, a3, b0r, b1r);
            }
        }
    }
    // flush: t[b][m][n], n contiguous (8 values -> 2x float4, 32B aligned)
#pragma unroll
    for (int nt = 0; nt < 4; nt++) {
        int col = wcol + nt * 8 + tg * 2;
        int r0 = b0 + wrow + g;
        float* base = g_t + ((size_t)r0 * 64 + col) * 128 + ng0;
#pragma unroll
        for (int s = 0; s < 4; s++) {
            float* dst = base + (s & 1) * 128 + (s >> 1) * (8 * 64 * 128);
            float4 v0 = make_float4(acc[0][nt][s], acc[1][nt][s], acc[2][nt][s], acc[3][nt][s]);
            float4 v1 = make_float4(acc[4][nt][s], acc[5][nt][s], acc[6][nt][s], acc[7][nt][s]);
            *(float4*)(dst) = v0;
            *(float4*)(dst + 4) = v1;
        }
    }
}

// ---------------- stage 2 ----------------
// CTA: 128 batch rows x 1 m-block. 256 thr = 8 warps, warp grid 4(row)x2(col),
// warp tile 32x64, K = 128.
#define S2P 132
__global__ __launch_bounds__(256, 1) void stage2_kernel(float* __restrict__ out) {
    extern __shared__ float sm2[];
    float* tts = sm2;                 // [128][S2P]
    float* w2s = sm2 + 128 * S2P;     // [128][S2P]
    int b0 = blockIdx.x * 128;
    int m  = blockIdx.y;
    int tid = threadIdx.x;
    int wid = tid >> 5, lane = tid & 31, g = lane >> 2, tg = lane & 3;
    int wrow = (wid & 3) * 32;
    int wcol = (wid >> 2) * 64;

    // load t rows (contiguous), tf32-round
    for (int idx = tid; idx < 4096; idx += 256) {
        int r = idx >> 5, c = idx & 31;
        float4 v = *(const float4*)(g_t + ((size_t)(b0 + r) * 64 + m) * 128 + c * 4);
        float* p = tts + r * S2P + c * 4;
        p[0] = f2tf_f(v.x); p[1] = f2tf_f(v.y); p[2] = f2tf_f(v.z); p[3] = f2tf_f(v.w);
    }
    // load w2[m] (already rounded)
    for (int idx = tid; idx < 4096; idx += 256) {
        int r = idx >> 5, c = idx & 31;
        float4 v = *(const float4*)(g_w2 + ((size_t)m * 128 + r) * 128 + c * 4);
        float* p = w2s + r * S2P + c * 4;
        p[0] = v.x; p[1] = v.y; p[2] = v.z; p[3] = v.w;
    }
    __syncthreads();

    float acc[2][8][4];
#pragma unroll
    for (int a = 0; a < 2; a++)
#pragma unroll
        for (int b = 0; b < 8; b++)
#pragma unroll
            for (int c = 0; c < 4; c++) acc[a][b][c] = 0.0f;

#pragma unroll
    for (int kk = 0; kk < 16; kk++) {
        int k0 = kk * 8;
        unsigned a[2][4];
#pragma unroll
        for (int mr = 0; mr < 2; mr++) {
            int r = wrow + mr * 16 + g;
            a[mr][0] = __float_as_uint(tts[r * S2P + k0 + tg]);
            a[mr][1] = __float_as_uint(tts[(r + 8) * S2P + k0 + tg]);
            a[mr][2] = __float_as_uint(tts[r * S2P + k0 + tg + 4]);
            a[mr][3] = __float_as_uint(tts[(r + 8) * S2P + k0 + tg + 4]);
        }
#pragma unroll
        for (int nt = 0; nt < 8; nt++) {
            int col = wcol + nt * 8 + g;
            unsigned b0r = __float_as_uint(w2s[(k0 + tg) * S2P + col]);
            unsigned b1r = __float_as_uint(w2s[(k0 + tg + 4) * S2P + col]);
#pragma unroll
            for (int mr = 0; mr < 2; mr++)
                mma_tf32(acc[mr][nt][0], acc[mr][nt][1], acc[mr][nt][2], acc[mr][nt][3],
                         a[mr][0], a[mr][1], a[mr][2], a[mr][3], b0r, b1r);
        }
    }

    // flush: out[b][m*128 + o]
#pragma unroll
    for (int mr = 0; mr < 2; mr++) {
#pragma unroll
        for (int nt = 0; nt < 8; nt++) {
            int col = wcol + nt * 8 + tg * 2;
            int r = b0 + wrow + mr * 16 + g;
            float* dst = out + (size_t)r * 8192 + m * 128 + col;
            *(float2*)dst = make_float2(acc[mr][nt][0], acc[mr][nt][1]);
            *(float2*)(dst + (size_t)8 * 8192) = make_float2(acc[mr][nt][2], acc[mr][nt][3]);
        }
    }
}

// ---------------- launch ----------------
extern "C" void kernel_launch(void* const* d_in, const int* in_sizes, int n_in,
                              void* d_out, int out_size) {
    const float* x = nullptr;
    const float* c1 = nullptr;
    const float* c2 = nullptr;
    for (int i = 0; i < n_in; i++) {
        if (in_sizes[i] == BROWS * 8192)            x  = (const float*)d_in[i];
        else if (in_sizes[i] == NB1 * I1 * MMID)    c1 = (const float*)d_in[i];
        else if (in_sizes[i] == MMID * NB1 * O2)    c2 = (const float*)d_in[i];
    }
    const int smem2 = 2 * 128 * S2P * sizeof(float);
    cudaFuncSetAttribute(stage2_kernel, cudaFuncAttributeMaxDynamicSharedMemorySize, smem2);

    softmax1_kernel<<<NB1, MMID>>>(c1);
    softmax2_kernel<<<MMID, O2>>>(c2);
    stage1_kernel<<<dim3(BROWS / 64, NB1 / 8), 256>>>(x);
    stage2_kernel<<<dim3(BROWS / 128, MMID), 256, smem2>>>((float*)d_out);
}

// round 3
// speedup vs baseline: 2.3342x; 2.3342x over previous
#include <cuda_runtime.h>
#include <cstdint>
#include <cstddef>

// Problem dims
#define BROWS 4096
#define NB1   128   // stage-1 blocks (n)
#define I1    64    // inputs per block 1 (k of stage 1)
#define MMID  64    // mid dim (m)
#define O2    128   // outputs per block 2 (o)

// t layout [b][m][n] (n contiguous), values tf32-pre-rounded
__device__ float g_t[(size_t)BROWS * MMID * NB1];   // 128 MB
__device__ float g_w1[NB1 * I1 * MMID];             // softmaxed, tf32-rounded, [n][i][m]
__device__ float g_w2[MMID * NB1 * O2];             // softmaxed, tf32-rounded, [m][n][o]

__device__ __forceinline__ float f2tf_f(float f) {
    unsigned u;
    asm("cvt.rna.tf32.f32 %0, %1;" : "=r"(u) : "f"(f));
    return __uint_as_float(u);
}

__device__ __forceinline__ void mma_tf32(float& d0, float& d1, float& d2, float& d3,
                                         unsigned a0, unsigned a1, unsigned a2, unsigned a3,
                                         unsigned b0, unsigned b1) {
    asm volatile(
        "mma.sync.aligned.m16n8k8.row.col.f32.tf32.tf32.f32 "
        "{%0,%1,%2,%3}, {%4,%5,%6,%7}, {%8,%9}, {%0,%1,%2,%3};"
        : "+f"(d0), "+f"(d1), "+f"(d2), "+f"(d3)
        : "r"(a0), "r"(a1), "r"(a2), "r"(a3), "r"(b0), "r"(b1));
}

__device__ __forceinline__ void cp16(void* dst_smem, const void* src) {
    unsigned d = (unsigned)__cvta_generic_to_shared(dst_smem);
    asm volatile("cp.async.cg.shared.global [%0], [%1], 16;" :: "r"(d), "l"(src));
}
__device__ __forceinline__ void cp_commit() { asm volatile("cp.async.commit_group;"); }
template<int N> __device__ __forceinline__ void cp_wait() {
    asm volatile("cp.async.wait_group %0;" :: "n"(N));
}

// ---------------- softmax precompute ----------------
__global__ void softmax1_kernel(const float* __restrict__ c1) {
    __shared__ float s[I1 * MMID];
    int n = blockIdx.x;          // 128
    int tid = threadIdx.x;       // 64
    const float4* src = (const float4*)(c1 + (size_t)n * I1 * MMID);
#pragma unroll
    for (int i = 0; i < 16; i++) ((float4*)s)[tid + i * 64] = src[tid + i * 64];
    __syncthreads();
    int m = tid;
    float v[I1];
    float mx = -1e30f;
#pragma unroll
    for (int i = 0; i < I1; i++) { v[i] = s[i * MMID + m] * 3.0f; mx = fmaxf(mx, v[i]); }
    float sum = 0.0f;
#pragma unroll
    for (int i = 0; i < I1; i++) { v[i] = expf(v[i] - mx); sum += v[i]; }
    float inv = 1.0f / sum;
    float* out = g_w1 + (size_t)n * I1 * MMID + m;
#pragma unroll
    for (int i = 0; i < I1; i++) out[i * MMID] = f2tf_f(v[i] * inv);
}

__global__ void softmax2_kernel(const float* __restrict__ c2) {
    extern __shared__ float s2[];  // 128*128 floats = 64 KB
    int m = blockIdx.x;            // 64
    int tid = threadIdx.x;         // 128
    const float4* src = (const float4*)(c2 + (size_t)m * NB1 * O2);
#pragma unroll
    for (int i = 0; i < 32; i++) ((float4*)s2)[tid + i * 128] = src[tid + i * 128];
    __syncthreads();
    int o = tid;
    float mx = -1e30f;
    for (int n = 0; n < NB1; n++) mx = fmaxf(mx, s2[n * O2 + o] * 3.0f);
    float sum = 0.0f;
    for (int n = 0; n < NB1; n++) sum += expf(s2[n * O2 + o] * 3.0f - mx);
    float inv = 1.0f / sum;
    for (int n = 0; n < NB1; n++)
        g_w2[((size_t)m * NB1 + n) * O2 + o] = f2tf_f(expf(s2[n * O2 + o] * 3.0f - mx) * inv);
}

// ---------------- stage 1 ----------------
// CTA: 64 b-rows x 8 n-blocks. 256 thr. 3-deep cp.async pipeline across n.
// Warp grid 4(row)x2(col), warp tile 16x32. acc[8][4][4].
#define S1P 68
__global__ __launch_bounds__(256, 1) void stage1_kernel(const float* __restrict__ x) {
    extern __shared__ float sm1[];
    float* xs = sm1;                 // [3][64*S1P]
    float* ws = sm1 + 3 * 64 * S1P;  // [3][64*S1P]
    int b0  = blockIdx.x * 64;
    int ng0 = blockIdx.y * 8;
    int tid = threadIdx.x;
    int wid = tid >> 5, lane = tid & 31, g = lane >> 2, tg = lane & 3;
    int wrow = (wid & 3) * 16;
    int wcol = (wid >> 2) * 32;

    auto issue = [&](int nn, int s) {
        int n = ng0 + nn;
        float* xd = xs + s * 64 * S1P;
        float* wd = ws + s * 64 * S1P;
#pragma unroll
        for (int i = 0; i < 4; i++) {
            int idx = tid + i * 256;           // 0..1023
            int r = idx >> 4, c = idx & 15;
            cp16(xd + r * S1P + c * 4, x + (size_t)(b0 + r) * 8192 + (size_t)n * 64 + c * 4);
            cp16(wd + r * S1P + c * 4, g_w1 + ((size_t)n * 64 + r) * 64 + c * 4);
        }
        cp_commit();
    };

    float acc[8][4][4];
#pragma unroll
    for (int a = 0; a < 8; a++)
#pragma unroll
        for (int b = 0; b < 4; b++)
#pragma unroll
            for (int c = 0; c < 4; c++) acc[a][b][c] = 0.0f;

    issue(0, 0);
    issue(1, 1);

#pragma unroll
    for (int nn = 0; nn < 8; nn++) {
        int s = nn % 3;
        if (nn < 6) { issue(nn + 2, (nn + 2) % 3); cp_wait<2>(); }
        else if (nn == 6) { cp_wait<1>(); }
        else { cp_wait<0>(); }
        __syncthreads();
        float* xb = xs + s * 64 * S1P;
        float* wb = ws + s * 64 * S1P;
#pragma unroll
        for (int kk = 0; kk < 8; kk++) {
            int k0 = kk * 8;
            unsigned a0 = __float_as_uint(f2tf_f(xb[(wrow + g) * S1P + k0 + tg]));
            unsigned a1 = __float_as_uint(f2tf_f(xb[(wrow + g + 8) * S1P + k0 + tg]));
            unsigned a2 = __float_as_uint(f2tf_f(xb[(wrow + g) * S1P + k0 + tg + 4]));
            unsigned a3 = __float_as_uint(f2tf_f(xb[(wrow + g + 8) * S1P + k0 + tg + 4]));
#pragma unroll
            for (int nt = 0; nt < 4; nt++) {
                int col = wcol + nt * 8 + g;
                unsigned b0r = __float_as_uint(wb[(k0 + tg) * S1P + col]);
                unsigned b1r = __float_as_uint(wb[(k0 + tg + 4) * S1P + col]);
                mma_tf32(acc[nn][nt][0], acc[nn][nt][1], acc[nn][nt][2], acc[nn][nt][3],
                         a0, a1, a2, a3, b0r, b1r);
            }
        }
        __syncthreads();
    }

    // flush: t[b][m][n], 8 consecutive n -> 2x float4 (32B runs), tf32-rounded
#pragma unroll
    for (int nt = 0; nt < 4; nt++) {
        int col = wcol + nt * 8 + tg * 2;
        int r0 = b0 + wrow + g;
        float* base = g_t + ((size_t)r0 * 64 + col) * 128 + ng0;
#pragma unroll
        for (int s = 0; s < 4; s++) {
            float* dst = base + (s & 1) * 128 + (s >> 1) * (8 * 64 * 128);
            float4 v0 = make_float4(f2tf_f(acc[0][nt][s]), f2tf_f(acc[1][nt][s]),
                                    f2tf_f(acc[2][nt][s]), f2tf_f(acc[3][nt][s]));
            float4 v1 = make_float4(f2tf_f(acc[4][nt][s]), f2tf_f(acc[5][nt][s]),
                                    f2tf_f(acc[6][nt][s]), f2tf_f(acc[7][nt][s]));
            *(float4*)(dst) = v0;
            *(float4*)(dst + 4) = v1;
        }
    }
}

// ---------------- stage 2 ----------------
// CTA: 128 b-rows x 1 m. 256 thr, warp tile 32x64. K=128 as 4 chunks of 32,
// 2-buffer cp.async pipeline. 2 CTAs/SM.
#define S2AP 36
#define S2BP 132
__global__ __launch_bounds__(256, 2) void stage2_kernel(float* __restrict__ out) {
    extern __shared__ float sm2[];
    float* As = sm2;                      // [2][128*S2AP]
    float* Bs = sm2 + 2 * 128 * S2AP;     // [2][32*S2BP]
    int b0 = blockIdx.x * 128;
    int m  = blockIdx.y;
    int tid = threadIdx.x;
    int wid = tid >> 5, lane = tid & 31, g = lane >> 2, tg = lane & 3;
    int wrow = (wid & 3) * 32;
    int wcol = (wid >> 2) * 64;

    auto issue = [&](int kc, int s) {
        int k0 = kc * 32;
        float* Ad = As + s * 128 * S2AP;
        float* Bd = Bs + s * 32 * S2BP;
#pragma unroll
        for (int i = 0; i < 4; i++) {       // A: 128 rows x 8 x 16B
            int idx = tid + i * 256;
            int r = idx >> 3, c = idx & 7;
            cp16(Ad + r * S2AP + c * 4, g_t + ((size_t)(b0 + r) * 64 + m) * 128 + k0 + c * 4);
        }
#pragma unroll
        for (int i = 0; i < 4; i++) {       // B: 32 rows x 32 x 16B
            int idx = tid + i * 256;
            int r = idx >> 5, c = idx & 31;
            cp16(Bd + r * S2BP + c * 4, g_w2 + ((size_t)m * 128 + k0 + r) * 128 + c * 4);
        }
        cp_commit();
    };

    float acc[2][8][4];
#pragma unroll
    for (int a = 0; a < 2; a++)
#pragma unroll
        for (int b = 0; b < 8; b++)
#pragma unroll
            for (int c = 0; c < 4; c++) acc[a][b][c] = 0.0f;

    issue(0, 0);

#pragma unroll
    for (int kc = 0; kc < 4; kc++) {
        int s = kc & 1;
        if (kc < 3) { issue(kc + 1, (kc + 1) & 1); cp_wait<1>(); }
        else { cp_wait<0>(); }
        __syncthreads();
        float* Ab = As + s * 128 * S2AP;
        float* Bb = Bs + s * 32 * S2BP;
#pragma unroll
        for (int kk = 0; kk < 4; kk++) {
            int k0 = kk * 8;
            unsigned a[2][4];
#pragma unroll
            for (int mr = 0; mr < 2; mr++) {
                int r = wrow + mr * 16 + g;
                a[mr][0] = __float_as_uint(Ab[r * S2AP + k0 + tg]);
                a[mr][1] = __float_as_uint(Ab[(r + 8) * S2AP + k0 + tg]);
                a[mr][2] = __float_as_uint(Ab[r * S2AP + k0 + tg + 4]);
                a[mr][3] = __float_as_uint(Ab[(r + 8) * S2AP + k0 + tg + 4]);
            }
#pragma unroll
            for (int nt = 0; nt < 8; nt++) {
                int col = wcol + nt * 8 + g;
                unsigned b0r = __float_as_uint(Bb[(k0 + tg) * S2BP + col]);
                unsigned b1r = __float_as_uint(Bb[(k0 + tg + 4) * S2BP + col]);
#pragma unroll
                for (int mr = 0; mr < 2; mr++)
                    mma_tf32(acc[mr][nt][0], acc[mr][nt][1], acc[mr][nt][2], acc[mr][nt][3],
                             a[mr][0], a[mr][1], a[mr][2], a[mr][3], b0r, b1r);
            }
        }
        __syncthreads();
    }

    // flush: out[b][m*128 + o]
#pragma unroll
    for (int mr = 0; mr < 2; mr++) {
#pragma unroll
        for (int nt = 0; nt < 8; nt++) {
            int col = wcol + nt * 8 + tg * 2;
            int r = b0 + wrow + mr * 16 + g;
            float* dst = out + (size_t)r * 8192 + m * 128 + col;
            *(float2*)dst = make_float2(acc[mr][nt][0], acc[mr][nt][1]);
            *(float2*)(dst + (size_t)8 * 8192) = make_float2(acc[mr][nt][2], acc[mr][nt][3]);
        }
    }
}

// ---------------- launch ----------------
extern "C" void kernel_launch(void* const* d_in, const int* in_sizes, int n_in,
                              void* d_out, int out_size) {
    const float* x = nullptr;
    const float* c1 = nullptr;
    const float* c2 = nullptr;
    for (int i = 0; i < n_in; i++) {
        if (in_sizes[i] == BROWS * 8192)            x  = (const float*)d_in[i];
        else if (in_sizes[i] == NB1 * I1 * MMID)    c1 = (const float*)d_in[i];
        else if (in_sizes[i] == MMID * NB1 * O2)    c2 = (const float*)d_in[i];
    }

    const int smem_sm2 = NB1 * O2 * sizeof(float);                       // 64 KB
    const int smem_s1  = 6 * 64 * S1P * sizeof(float);                   // ~102 KB
    const int smem_s2  = (2 * 128 * S2AP + 2 * 32 * S2BP) * sizeof(float); // ~69 KB
    cudaFuncSetAttribute(softmax2_kernel, cudaFuncAttributeMaxDynamicSharedMemorySize, smem_sm2);
    cudaFuncSetAttribute(stage1_kernel,   cudaFuncAttributeMaxDynamicSharedMemorySize, smem_s1);
    cudaFuncSetAttribute(stage2_kernel,   cudaFuncAttributeMaxDynamicSharedMemorySize, smem_s2);

    softmax1_kernel<<<NB1, MMID>>>(c1);
    softmax2_kernel<<<MMID, O2, smem_sm2>>>(c2);
    stage1_kernel<<<dim3(BROWS / 64, NB1 / 8), 256, smem_s1>>>(x);
    stage2_kernel<<<dim3(BROWS / 128, MMID), 256, smem_s2>>>((float*)d_out);
}

// round 4
// speedup vs baseline: 2.8736x; 1.2311x over previous
#include <cuda_runtime.h>
#include <cstdint>
#include <cstddef>

// Problem dims
#define BROWS 4096
#define NB1   128
#define I1    64
#define MMID  64
#define O2    128
#define BCH   1024   // batch chunk (t stays L2-resident)
#define NCHK  4

// t chunk layout [b_local][m][n] (n contiguous), tf32-pre-rounded. 32 MB, reused per chunk.
__device__ float g_t[(size_t)BCH * MMID * NB1];
__device__ float g_w1[NB1 * MMID * I1];   // TRANSPOSED: [n][m][i], softmaxed+tf32-rounded
__device__ float g_w2[MMID * O2 * NB1];   // TRANSPOSED: [m][o][n], softmaxed+tf32-rounded

__device__ __forceinline__ float f2tf_f(float f) {
    unsigned u;
    asm("cvt.rna.tf32.f32 %0, %1;" : "=r"(u) : "f"(f));
    return __uint_as_float(u);
}
__device__ __forceinline__ unsigned f2tf_u(unsigned x) {
    unsigned r;
    asm("cvt.rna.tf32.f32 %0, %1;" : "=r"(r) : "f"(__uint_as_float(x)));
    return r;
}

__device__ __forceinline__ void mma_tf32(float& d0, float& d1, float& d2, float& d3,
                                         unsigned a0, unsigned a1, unsigned a2, unsigned a3,
                                         unsigned b0, unsigned b1) {
    asm volatile(
        "mma.sync.aligned.m16n8k8.row.col.f32.tf32.tf32.f32 "
        "{%0,%1,%2,%3}, {%4,%5,%6,%7}, {%8,%9}, {%0,%1,%2,%3};"
        : "+f"(d0), "+f"(d1), "+f"(d2), "+f"(d3)
        : "r"(a0), "r"(a1), "r"(a2), "r"(a3), "r"(b0), "r"(b1));
}

__device__ __forceinline__ void ldsm4(unsigned& r0, unsigned& r1, unsigned& r2, unsigned& r3,
                                      const float* p) {
    unsigned a = (unsigned)__cvta_generic_to_shared(p);
    asm volatile("ldmatrix.sync.aligned.m8n8.x4.shared.b16 {%0,%1,%2,%3}, [%4];"
                 : "=r"(r0), "=r"(r1), "=r"(r2), "=r"(r3) : "r"(a));
}

__device__ __forceinline__ void cp16(void* dst_smem, const void* src) {
    unsigned d = (unsigned)__cvta_generic_to_shared(dst_smem);
    asm volatile("cp.async.cg.shared.global [%0], [%1], 16;" :: "r"(d), "l"(src));
}
__device__ __forceinline__ void cp_commit() { asm volatile("cp.async.commit_group;"); }
template<int N> __device__ __forceinline__ void cp_wait() {
    asm volatile("cp.async.wait_group %0;" :: "n"(N));
}

// ---------------- softmax precompute ----------------
// g_w1[n][m][i] = softmax over i of 3*c1[n,i,m]   (transposed output)
__global__ void softmax1_kernel(const float* __restrict__ c1) {
    __shared__ float s[I1 * MMID];     // in  [i][m]
    __shared__ float so[MMID * 68];    // out [m][i], padded
    int n = blockIdx.x;
    int tid = threadIdx.x;             // 64
    const float4* src = (const float4*)(c1 + (size_t)n * I1 * MMID);
#pragma unroll
    for (int i = 0; i < 16; i++) ((float4*)s)[tid + i * 64] = src[tid + i * 64];
    __syncthreads();
    int m = tid;
    float v[I1];
    float mx = -1e30f;
#pragma unroll
    for (int i = 0; i < I1; i++) { v[i] = s[i * MMID + m] * 3.0f; mx = fmaxf(mx, v[i]); }
    float sum = 0.0f;
#pragma unroll
    for (int i = 0; i < I1; i++) { v[i] = expf(v[i] - mx); sum += v[i]; }
    float inv = 1.0f / sum;
#pragma unroll
    for (int i = 0; i < I1; i++) so[m * 68 + i] = f2tf_f(v[i] * inv);
    __syncthreads();
    // coalesced copy out: [m][i] contiguous i
    float* dst = g_w1 + (size_t)n * MMID * I1;
#pragma unroll
    for (int t = 0; t < 16; t++) {
        int idx = tid + t * 64;        // 0..1023 float4s
        int r = idx >> 4, c = idx & 15;
        *(float4*)(dst + r * 64 + c * 4) = *(float4*)(so + r * 68 + c * 4);
    }
}

// g_w2[m][o][n] = softmax over n of 3*c2[m,n,o]   (transposed output)
__global__ void softmax2_kernel(const float* __restrict__ c2) {
    extern __shared__ float sm[];
    float* sin = sm;                    // [n][o] 128x128
    float* sout = sm + NB1 * O2;        // [o][n] 128x132 padded
    int m = blockIdx.x;
    int tid = threadIdx.x;              // 128
    const float4* src = (const float4*)(c2 + (size_t)m * NB1 * O2);
#pragma unroll
    for (int i = 0; i < 32; i++) ((float4*)sin)[tid + i * 128] = src[tid + i * 128];
    __syncthreads();
    int o = tid;
    float mx = -1e30f;
    for (int n = 0; n < NB1; n++) mx = fmaxf(mx, sin[n * O2 + o] * 3.0f);
    float sum = 0.0f;
    for (int n = 0; n < NB1; n++) sum += expf(sin[n * O2 + o] * 3.0f - mx);
    float inv = 1.0f / sum;
    for (int n = 0; n < NB1; n++)
        sout[o * 132 + n] = f2tf_f(expf(sin[n * O2 + o] * 3.0f - mx) * inv);
    __syncthreads();
    float* dst = g_w2 + (size_t)m * O2 * NB1;
#pragma unroll
    for (int t = 0; t < 32; t++) {
        int idx = tid + t * 128;        // 0..4095 float4s
        int r = idx >> 5, c = idx & 31;
        *(float4*)(dst + r * 128 + c * 4) = *(float4*)(sout + r * 132 + c * 4);
    }
}

// ---------------- stage 1 ----------------
// CTA: 64 b-rows x 4 n-blocks, 256 thr. Warp grid 4(b:16) x 2(m:32).
// Double-buffered cp.async across the 4-n loop. ldmatrix fragment loads.
// acc[4][4][4] = 64 regs -> 2 CTAs/SM.
#define S1P 68
__global__ __launch_bounds__(256, 2) void stage1_kernel(const float* __restrict__ x, int chunk) {
    extern __shared__ float sm1[];
    float* As = sm1;                   // [2][64*S1P]
    float* Bs = sm1 + 2 * 64 * S1P;    // [2][64*S1P]
    int b0l = blockIdx.x * 64;
    int bg0 = chunk * BCH + b0l;
    int ng0 = blockIdx.y * 4;
    int tid = threadIdx.x;
    int wid = tid >> 5, lane = tid & 31, g = lane >> 2, tg = lane & 3;
    int sub = lane >> 3, r8 = lane & 7;
    int wrow = (wid & 3) * 16;
    int wcol = (wid >> 2) * 32;

    auto issue = [&](int nn, int s) {
        int n = ng0 + nn;
        float* Ad = As + s * 64 * S1P;
        float* Bd = Bs + s * 64 * S1P;
#pragma unroll
        for (int i = 0; i < 4; i++) {
            int idx = tid + i * 256;
            int r = idx >> 4, c = idx & 15;
            cp16(Ad + r * S1P + c * 4, x + (size_t)(bg0 + r) * 8192 + (size_t)n * 64 + c * 4);
            cp16(Bd + r * S1P + c * 4, g_w1 + ((size_t)n * 64 + r) * 64 + c * 4); // [n][m][i]
        }
        cp_commit();
    };

    float acc[4][4][4];
#pragma unroll
    for (int a = 0; a < 4; a++)
#pragma unroll
        for (int b = 0; b < 4; b++)
#pragma unroll
            for (int c = 0; c < 4; c++) acc[a][b][c] = 0.0f;

    issue(0, 0);

#pragma unroll
    for (int nn = 0; nn < 4; nn++) {
        int s = nn & 1;
        if (nn < 3) { issue(nn + 1, (nn + 1) & 1); cp_wait<1>(); }
        else cp_wait<0>();
        __syncthreads();
        float* Ab = As + s * 64 * S1P;
        float* Bb = Bs + s * 64 * S1P;
#pragma unroll
        for (int kk = 0; kk < 8; kk++) {
            int k0 = kk * 8;
            unsigned a0, a1, a2, a3;
            ldsm4(a0, a1, a2, a3,
                  Ab + (wrow + (sub & 1) * 8 + r8) * S1P + k0 + (sub >> 1) * 4);
            a0 = f2tf_u(a0); a1 = f2tf_u(a1); a2 = f2tf_u(a2); a3 = f2tf_u(a3);
#pragma unroll
            for (int pair = 0; pair < 2; pair++) {
                unsigned b0a, b1a, b0b, b1b;
                ldsm4(b0a, b1a, b0b, b1b,
                      Bb + (wcol + pair * 16 + (sub >> 1) * 8 + r8) * S1P + k0 + (sub & 1) * 4);
                mma_tf32(acc[nn][2*pair][0], acc[nn][2*pair][1], acc[nn][2*pair][2], acc[nn][2*pair][3],
                         a0, a1, a2, a3, b0a, b1a);
                mma_tf32(acc[nn][2*pair+1][0], acc[nn][2*pair+1][1], acc[nn][2*pair+1][2], acc[nn][2*pair+1][3],
                         a0, a1, a2, a3, b0b, b1b);
            }
        }
        __syncthreads();
    }

    // flush: t[b_local][m][ng0..ng0+3] as float4, tf32-rounded
#pragma unroll
    for (int nt = 0; nt < 4; nt++) {
#pragma unroll
        for (int rr = 0; rr < 2; rr++) {
#pragma unroll
            for (int c = 0; c < 2; c++) {
                int row = wrow + g + rr * 8;
                int col = wcol + nt * 8 + tg * 2 + c;
                int s = rr * 2 + c;
                float4 v = make_float4(f2tf_f(acc[0][nt][s]), f2tf_f(acc[1][nt][s]),
                                       f2tf_f(acc[2][nt][s]), f2tf_f(acc[3][nt][s]));
                *(float4*)(g_t + ((size_t)(b0l + row) * 64 + col) * 128 + ng0) = v;
            }
        }
    }
}

// ---------------- stage 2 ----------------
// CTA: 128 b-rows x 1 m, 256 thr. Warp grid 4(b:32) x 2(o:64).
// K=128 in 4 chunks of 32, double-buffered. ldmatrix fragment loads. 2 CTAs/SM.
#define S2P 36
__global__ __launch_bounds__(256, 2) void stage2_kernel(float* __restrict__ out, int chunk) {
    extern __shared__ float sm2[];
    float* As = sm2;                    // [2][128*S2P]
    float* Bs = sm2 + 2 * 128 * S2P;    // [2][128*S2P]
    int b0l = blockIdx.x * 128;
    int bg0 = chunk * BCH + b0l;
    int m  = blockIdx.y;
    int tid = threadIdx.x;
    int wid = tid >> 5, lane = tid & 31, g = lane >> 2, tg = lane & 3;
    int sub = lane >> 3, r8 = lane & 7;
    int wrow = (wid & 3) * 32;
    int wcol = (wid >> 2) * 64;

    auto issue = [&](int kc, int s) {
        int k0 = kc * 32;
        float* Ad = As + s * 128 * S2P;
        float* Bd = Bs + s * 128 * S2P;
#pragma unroll
        for (int i = 0; i < 4; i++) {
            int idx = tid + i * 256;
            int r = idx >> 3, c = idx & 7;
            cp16(Ad + r * S2P + c * 4, g_t + ((size_t)(b0l + r) * 64 + m) * 128 + k0 + c * 4);
            cp16(Bd + r * S2P + c * 4, g_w2 + ((size_t)m * 128 + r) * 128 + k0 + c * 4); // [m][o][n]
        }
        cp_commit();
    };

    float acc[2][8][4];
#pragma unroll
    for (int a = 0; a < 2; a++)
#pragma unroll
        for (int b = 0; b < 8; b++)
#pragma unroll
            for (int c = 0; c < 4; c++) acc[a][b][c] = 0.0f;

    issue(0, 0);

#pragma unroll
    for (int kc = 0; kc < 4; kc++) {
        int s = kc & 1;
        if (kc < 3) { issue(kc + 1, (kc + 1) & 1); cp_wait<1>(); }
        else cp_wait<0>();
        __syncthreads();
        float* Ab = As + s * 128 * S2P;
        float* Bb = Bs + s * 128 * S2P;
#pragma unroll
        for (int kk = 0; kk < 4; kk++) {
            int k0 = kk * 8;
            unsigned am[2][4];
#pragma unroll
            for (int mr = 0; mr < 2; mr++)
                ldsm4(am[mr][0], am[mr][1], am[mr][2], am[mr][3],
                      Ab + (wrow + mr * 16 + (sub & 1) * 8 + r8) * S2P + k0 + (sub >> 1) * 4);
#pragma unroll
            for (int pair = 0; pair < 4; pair++) {
                unsigned b0a, b1a, b0b, b1b;
                ldsm4(b0a, b1a, b0b, b1b,
                      Bb + (wcol + pair * 16 + (sub >> 1) * 8 + r8) * S2P + k0 + (sub & 1) * 4);
#pragma unroll
                for (int mr = 0; mr < 2; mr++) {
                    mma_tf32(acc[mr][2*pair][0], acc[mr][2*pair][1], acc[mr][2*pair][2], acc[mr][2*pair][3],
                             am[mr][0], am[mr][1], am[mr][2], am[mr][3], b0a, b1a);
                    mma_tf32(acc[mr][2*pair+1][0], acc[mr][2*pair+1][1], acc[mr][2*pair+1][2], acc[mr][2*pair+1][3],
                             am[mr][0], am[mr][1], am[mr][2], am[mr][3], b0b, b1b);
                }
            }
        }
        __syncthreads();
    }

    // flush: out[b][m*128 + o]
#pragma unroll
    for (int mr = 0; mr < 2; mr++) {
#pragma unroll
        for (int nt = 0; nt < 8; nt++) {
            int col = wcol + nt * 8 + tg * 2;
            int r = bg0 + wrow + mr * 16 + g;
            float* dst = out + (size_t)r * 8192 + m * 128 + col;
            *(float2*)dst = make_float2(acc[mr][nt][0], acc[mr][nt][1]);
            *(float2*)(dst + (size_t)8 * 8192) = make_float2(acc[mr][nt][2], acc[mr][nt][3]);
        }
    }
}

// ---------------- launch ----------------
extern "C" void kernel_launch(void* const* d_in, const int* in_sizes, int n_in,
                              void* d_out, int out_size) {
    const float* x = nullptr;
    const float* c1 = nullptr;
    const float* c2 = nullptr;
    for (int i = 0; i < n_in; i++) {
        if (in_sizes[i] == BROWS * 8192)            x  = (const float*)d_in[i];
        else if (in_sizes[i] == NB1 * I1 * MMID)    c1 = (const float*)d_in[i];
        else if (in_sizes[i] == MMID * NB1 * O2)    c2 = (const float*)d_in[i];
    }

    const int smem_sm2 = (NB1 * O2 + O2 * 132) * sizeof(float);   // 130 KB
    const int smem_s1  = 4 * 64 * S1P * sizeof(float);            // ~68 KB
    const int smem_s2  = 4 * 128 * S2P * sizeof(float);           // 72 KB
    cudaFuncSetAttribute(softmax2_kernel, cudaFuncAttributeMaxDynamicSharedMemorySize, smem_sm2);
    cudaFuncSetAttribute(stage1_kernel,   cudaFuncAttributeMaxDynamicSharedMemorySize, smem_s1);
    cudaFuncSetAttribute(stage2_kernel,   cudaFuncAttributeMaxDynamicSharedMemorySize, smem_s2);

    softmax1_kernel<<<NB1, MMID>>>(c1);
    softmax2_kernel<<<MMID, O2, smem_sm2>>>(c2);
    for (int c = 0; c < NCHK; c++) {
        stage1_kernel<<<dim3(BCH / 64, NB1 / 4), 256, smem_s1>>>(x, c);
        stage2_kernel<<<dim3(BCH / 128, MMID), 256, smem_s2>>>((float*)d_out, c);
    }
}

// round 9
// speedup vs baseline: 3.2492x; 1.1307x over previous
#include <cuda_runtime.h>
#include <cuda_fp16.h>
#include <cstdint>
#include <cstddef>

// Problem dims
#define BROWS 4096
#define NB1   128
#define I1    64
#define MMID  64
#define O2    128
#define BCH   1024   // batch chunk (t chunk = 32 MB, L2-resident)
#define NCHK  4

// t chunk layout [b_local][m][n] (n contiguous), raw fp32
__device__ float  g_t[(size_t)BCH * MMID * NB1];     // 32 MB
__device__ __half g_w1h[NB1 * MMID * I1];            // [n][m][i] softmaxed fp16
__device__ __half g_w2h[MMID * O2 * NB1];            // [m][o][n] softmaxed fp16

__device__ __forceinline__ unsigned pack2(float x, float y) {
    __half2 h = __floats2half2_rn(x, y);
    return *(unsigned*)&h;
}

__device__ __forceinline__ void mma_f16(float& d0, float& d1, float& d2, float& d3,
                                        unsigned a0, unsigned a1, unsigned a2, unsigned a3,
                                        unsigned b0, unsigned b1) {
    asm volatile(
        "mma.sync.aligned.m16n8k16.row.col.f32.f16.f16.f32 "
        "{%0,%1,%2,%3}, {%4,%5,%6,%7}, {%8,%9}, {%0,%1,%2,%3};"
        : "+f"(d0), "+f"(d1), "+f"(d2), "+f"(d3)
        : "r"(a0), "r"(a1), "r"(a2), "r"(a3), "r"(b0), "r"(b1));
}

__device__ __forceinline__ void ldsm4(unsigned& r0, unsigned& r1, unsigned& r2, unsigned& r3,
                                      const void* p) {
    unsigned a = (unsigned)__cvta_generic_to_shared(p);
    asm volatile("ldmatrix.sync.aligned.m8n8.x4.shared.b16 {%0,%1,%2,%3}, [%4];"
                 : "=r"(r0), "=r"(r1), "=r"(r2), "=r"(r3) : "r"(a));
}

__device__ __forceinline__ void cp16(void* dst_smem, const void* src) {
    unsigned d = (unsigned)__cvta_generic_to_shared(dst_smem);
    asm volatile("cp.async.cg.shared.global [%0], [%1], 16;" :: "r"(d), "l"(src));
}
__device__ __forceinline__ void cp_commit() { asm volatile("cp.async.commit_group;"); }
template<int N> __device__ __forceinline__ void cp_wait() {
    asm volatile("cp.async.wait_group %0;" :: "n"(N));
}

// ---------------- softmax precompute ----------------
// g_w1h[n][m][i] = softmax_i of 3*c1[n,i,m]
__global__ void softmax1_kernel(const float* __restrict__ c1) {
    __shared__ float s[I1 * MMID];
    __shared__ float so[MMID * 68];    // [m][i] padded
    int n = blockIdx.x;
    int tid = threadIdx.x;             // 64
    const float4* src = (const float4*)(c1 + (size_t)n * I1 * MMID);
#pragma unroll
    for (int i = 0; i < 16; i++) ((float4*)s)[tid + i * 64] = src[tid + i * 64];
    __syncthreads();
    int m = tid;
    float v[I1];
    float mx = -1e30f;
#pragma unroll
    for (int i = 0; i < I1; i++) { v[i] = s[i * MMID + m] * 3.0f; mx = fmaxf(mx, v[i]); }
    float sum = 0.0f;
#pragma unroll
    for (int i = 0; i < I1; i++) { v[i] = expf(v[i] - mx); sum += v[i]; }
    float inv = 1.0f / sum;
#pragma unroll
    for (int i = 0; i < I1; i++) so[m * 68 + i] = v[i] * inv;
    __syncthreads();
    __half* dst = g_w1h + (size_t)n * MMID * I1;
#pragma unroll
    for (int t = 0; t < 16; t++) {
        int idx = tid + t * 64;        // 1024 float4 units
        int r = idx >> 4, c = idx & 15;
        float4 q = *(float4*)(so + r * 68 + c * 4);
        uint2 h = make_uint2(pack2(q.x, q.y), pack2(q.z, q.w));
        *(uint2*)(dst + r * 64 + c * 4) = h;
    }
}

// g_w2h[m][o][n] = softmax_n of 3*c2[m,n,o]
__global__ void softmax2_kernel(const float* __restrict__ c2) {
    extern __shared__ float sm[];
    float* sin = sm;                    // [n][o]
    float* sout = sm + NB1 * O2;        // [o][n] pitch 132
    int m = blockIdx.x;
    int tid = threadIdx.x;              // 128
    const float4* src = (const float4*)(c2 + (size_t)m * NB1 * O2);
#pragma unroll
    for (int i = 0; i < 32; i++) ((float4*)sin)[tid + i * 128] = src[tid + i * 128];
    __syncthreads();
    int o = tid;
    float mx = -1e30f;
    for (int n = 0; n < NB1; n++) mx = fmaxf(mx, sin[n * O2 + o] * 3.0f);
    float sum = 0.0f;
    for (int n = 0; n < NB1; n++) sum += expf(sin[n * O2 + o] * 3.0f - mx);
    float inv = 1.0f / sum;
    for (int n = 0; n < NB1; n++)
        sout[o * 132 + n] = expf(sin[n * O2 + o] * 3.0f - mx) * inv;
    __syncthreads();
    __half* dst = g_w2h + (size_t)m * O2 * NB1;
#pragma unroll
    for (int t = 0; t < 32; t++) {
        int idx = tid + t * 128;        // 4096 float4 units
        int r = idx >> 5, c = idx & 31;
        float4 q = *(float4*)(sout + r * 132 + c * 4);
        uint2 h = make_uint2(pack2(q.x, q.y), pack2(q.z, q.w));
        *(uint2*)(dst + r * 128 + c * 4) = h;
    }
}

// ---------------- stage 1 (fp16 mma) ----------------
// CTA: 64 b-rows x 4 n-blocks, 256 thr. Warp grid 4(b:16) x 2(m:32).
// A = x tile 64x64 (LDG f32 -> cvt fp16 -> STS), B = w1h (cp.async, FULL 8KB).
// Double-buffered across n; cpB issued AFTER the iteration barrier (race-safe).
#define S1PITCH 144                     // bytes per row (72 halves)
#define S1TILE  (64 * S1PITCH)          // 9216 B
#define S1BUF   (2 * S1TILE)            // A + B per stage
__global__ __launch_bounds__(256, 2) void stage1_kernel(const float* __restrict__ x, int chunk) {
    extern __shared__ char sm1[];
    int b0l = blockIdx.x * 64;
    int bg0 = chunk * BCH + b0l;
    int ng0 = blockIdx.y * 4;
    int tid = threadIdx.x;
    int wid = tid >> 5, lane = tid & 31, g = lane >> 2, tg = lane & 3;
    int wrow = (wid & 3) * 16;
    int wcol = (wid >> 2) * 32;

    float4 areg[4];
    auto ldgA = [&](int j) {
        int n = ng0 + j;
#pragma unroll
        for (int i = 0; i < 4; i++) {
            int idx = tid + i * 256;            // 1024 float4 units
            int r = idx >> 4, c = idx & 15;
            areg[i] = *(const float4*)(x + (size_t)(bg0 + r) * 8192 + n * 64 + c * 4);
        }
    };
    auto stsA = [&](int s) {
        char* Ab = sm1 + s * S1BUF;
#pragma unroll
        for (int i = 0; i < 4; i++) {
            int idx = tid + i * 256;
            int r = idx >> 4, c = idx & 15;
            uint2 h = make_uint2(pack2(areg[i].x, areg[i].y), pack2(areg[i].z, areg[i].w));
            *(uint2*)(Ab + r * S1PITCH + c * 8) = h;
        }
    };
    auto cpB = [&](int j, int s) {
        int n = ng0 + j;
        char* Bb = sm1 + s * S1BUF + S1TILE;
#pragma unroll
        for (int i = 0; i < 2; i++) {
            int idx = tid + i * 256;            // 512 16B units: 64 rows x 8
            int r = idx >> 3, c = idx & 7;
            cp16(Bb + r * S1PITCH + c * 16, g_w1h + ((size_t)n * 64 + r) * 64 + c * 8);
        }
        cp_commit();
    };

    float acc[4][4][4];
#pragma unroll
    for (int a = 0; a < 4; a++)
#pragma unroll
        for (int b = 0; b < 4; b++)
#pragma unroll
            for (int c = 0; c < 4; c++) acc[a][b][c] = 0.0f;

    ldgA(0); stsA(0); cpB(0, 0);

    int arow = wrow + (lane & 15);
    int acolh = (lane >> 4) * 8;                         // halves
    int brow_base = ((lane >> 4) << 3) + (lane & 7);
    int bcolh = ((lane >> 3) & 1) * 8;

#pragma unroll
    for (int j = 0; j < 4; j++) {
        int s = j & 1, o = s ^ 1;
        if (j < 3) ldgA(j + 1);                // global latency overlapped
        cp_wait<0>();
        __syncthreads();                        // all j-1 readers done; buffers visible
        if (j < 3) cpB(j + 1, o);               // safe: after barrier; overlaps compute
        char* Ab = sm1 + s * S1BUF;
        char* Bb = Ab + S1TILE;
#pragma unroll
        for (int kk = 0; kk < 4; kk++) {
            int k0 = kk * 16;
            unsigned a0, a1, a2, a3;
            ldsm4(a0, a1, a2, a3, Ab + arow * S1PITCH + (k0 + acolh) * 2);
#pragma unroll
            for (int p = 0; p < 2; p++) {
                unsigned b0g0, b1g0, b0g1, b1g1;
                ldsm4(b0g0, b1g0, b0g1, b1g1,
                      Bb + (wcol + p * 16 + brow_base) * S1PITCH + (k0 + bcolh) * 2);
                mma_f16(acc[j][2*p][0], acc[j][2*p][1], acc[j][2*p][2], acc[j][2*p][3],
                        a0, a1, a2, a3, b0g0, b1g0);
                mma_f16(acc[j][2*p+1][0], acc[j][2*p+1][1], acc[j][2*p+1][2], acc[j][2*p+1][3],
                        a0, a1, a2, a3, b0g1, b1g1);
            }
        }
        if (j < 3) stsA(o);                     // safe: barrier at j cleared j-1 readers
    }

    // flush: t[b_local][m][ng0..ng0+3] as float4 (raw fp32)
#pragma unroll
    for (int nt = 0; nt < 4; nt++) {
#pragma unroll
        for (int rr = 0; rr < 2; rr++) {
#pragma unroll
            for (int c = 0; c < 2; c++) {
                int row = wrow + g + rr * 8;
                int col = wcol + nt * 8 + tg * 2 + c;
                int s = rr * 2 + c;
                float4 v = make_float4(acc[0][nt][s], acc[1][nt][s],
                                       acc[2][nt][s], acc[3][nt][s]);
                *(float4*)(g_t + ((size_t)(b0l + row) * 64 + col) * 128 + ng0) = v;
            }
        }
    }
}

// ---------------- stage 2 (fp16 mma) ----------------
// CTA: 128 b-rows x 1 m, 256 thr. Warp grid 4(b:32) x 2(o:64).
// K=128 in 4 chunks of 32, double-buffered. A = t (LDG f32->cvt->STS), B = w2h (cp.async).
#define S2PITCH 80                      // bytes per row (40 halves)
#define S2TILE  (128 * S2PITCH)         // 10240 B
#define S2BUF   (2 * S2TILE)
__global__ __launch_bounds__(256, 2) void stage2_kernel(float* __restrict__ out, int chunk) {
    extern __shared__ char sm2[];
    int b0l = blockIdx.x * 128;
    int bg0 = chunk * BCH + b0l;
    int m  = blockIdx.y;
    int tid = threadIdx.x;
    int wid = tid >> 5, lane = tid & 31, g = lane >> 2, tg = lane & 3;
    int wrow = (wid & 3) * 32;
    int wcol = (wid >> 2) * 64;

    float4 areg[4];
    auto ldgA = [&](int kc) {
        int k0 = kc * 32;
#pragma unroll
        for (int i = 0; i < 4; i++) {
            int idx = tid + i * 256;             // 1024 units: 128 rows x 8
            int r = idx >> 3, c = idx & 7;
            areg[i] = *(const float4*)(g_t + ((size_t)(b0l + r) * 64 + m) * 128 + k0 + c * 4);
        }
    };
    auto stsA = [&](int s) {
        char* Ab = sm2 + s * S2BUF;
#pragma unroll
        for (int i = 0; i < 4; i++) {
            int idx = tid + i * 256;
            int r = idx >> 3, c = idx & 7;
            uint2 h = make_uint2(pack2(areg[i].x, areg[i].y), pack2(areg[i].z, areg[i].w));
            *(uint2*)(Ab + r * S2PITCH + c * 8) = h;
        }
    };
    auto cpB = [&](int kc, int s) {
        char* Bb = sm2 + s * S2BUF + S2TILE;
#pragma unroll
        for (int i = 0; i < 2; i++) {            // 512 units: 128 rows x 4
            int idx = tid + i * 256;
            int r = idx >> 2, c = idx & 3;
            cp16(Bb + r * S2PITCH + c * 16,
                 g_w2h + ((size_t)m * 128 + r) * 128 + kc * 32 + c * 8);
        }
        cp_commit();
    };

    float acc[2][8][4];
#pragma unroll
    for (int a = 0; a < 2; a++)
#pragma unroll
        for (int b = 0; b < 8; b++)
#pragma unroll
            for (int c = 0; c < 4; c++) acc[a][b][c] = 0.0f;

    ldgA(0); stsA(0); cpB(0, 0);

    int arow_off = lane & 15;
    int acolh = (lane >> 4) * 8;
    int brow_base = ((lane >> 4) << 3) + (lane & 7);
    int bcolh = ((lane >> 3) & 1) * 8;

#pragma unroll
    for (int kc = 0; kc < 4; kc++) {
        int s = kc & 1, o = s ^ 1;
        if (kc < 3) ldgA(kc + 1);
        cp_wait<0>();
        __syncthreads();
        if (kc < 3) cpB(kc + 1, o);             // after barrier: race-safe
        char* Ab = sm2 + s * S2BUF;
        char* Bb = Ab + S2TILE;
#pragma unroll
        for (int kk = 0; kk < 2; kk++) {
            int k0 = kk * 16;
            unsigned am[2][4];
#pragma unroll
            for (int mr = 0; mr < 2; mr++)
                ldsm4(am[mr][0], am[mr][1], am[mr][2], am[mr][3],
                      Ab + (wrow + mr * 16 + arow_off) * S2PITCH + (k0 + acolh) * 2);
#pragma unroll
            for (int p = 0; p < 4; p++) {
                unsigned b0g0, b1g0, b0g1, b1g1;
                ldsm4(b0g0, b1g0, b0g1, b1g1,
                      Bb + (wcol + p * 16 + brow_base) * S2PITCH + (k0 + bcolh) * 2);
#pragma unroll
                for (int mr = 0; mr < 2; mr++) {
                    mma_f16(acc[mr][2*p][0], acc[mr][2*p][1], acc[mr][2*p][2], acc[mr][2*p][3],
                            am[mr][0], am[mr][1], am[mr][2], am[mr][3], b0g0, b1g0);
                    mma_f16(acc[mr][2*p+1][0], acc[mr][2*p+1][1], acc[mr][2*p+1][2], acc[mr][2*p+1][3],
                            am[mr][0], am[mr][1], am[mr][2], am[mr][3], b0g1, b1g1);
                }
            }
        }
        if (kc < 3) stsA(o);
    }

    // flush: out[b][m*128 + o]
#pragma unroll
    for (int mr = 0; mr < 2; mr++) {
#pragma unroll
        for (int nt = 0; nt < 8; nt++) {
            int col = wcol + nt * 8 + tg * 2;
            int r = bg0 + wrow + mr * 16 + g;
            float* dst = out + (size_t)r * 8192 + m * 128 + col;
            *(float2*)dst = make_float2(acc[mr][nt][0], acc[mr][nt][1]);
            *(float2*)(dst + (size_t)8 * 8192) = make_float2(acc[mr][nt][2], acc[mr][nt][3]);
        }
    }
}

// ---------------- launch ----------------
extern "C" void kernel_launch(void* const* d_in, const int* in_sizes, int n_in,
                              void* d_out, int out_size) {
    const float* x = nullptr;
    const float* c1 = nullptr;
    const float* c2 = nullptr;
    for (int i = 0; i < n_in; i++) {
        if (in_sizes[i] == BROWS * 8192)            x  = (const float*)d_in[i];
        else if (in_sizes[i] == NB1 * I1 * MMID)    c1 = (const float*)d_in[i];
        else if (in_sizes[i] == MMID * NB1 * O2)    c2 = (const float*)d_in[i];
    }

    const int smem_sm2 = (NB1 * O2 + O2 * 132) * sizeof(float);   // ~130 KB
    const int smem_s1  = 2 * S1BUF;                               // 36.9 KB
    const int smem_s2  = 2 * S2BUF;                               // 40.9 KB
    cudaFuncSetAttribute(softmax2_kernel, cudaFuncAttributeMaxDynamicSharedMemorySize, smem_sm2);
    cudaFuncSetAttribute(stage1_kernel,   cudaFuncAttributeMaxDynamicSharedMemorySize, smem_s1);
    cudaFuncSetAttribute(stage2_kernel,   cudaFuncAttributeMaxDynamicSharedMemorySize, smem_s2);

    softmax1_kernel<<<NB1, MMID>>>(c1);
    softmax2_kernel<<<MMID, O2, smem_sm2>>>(c2);
    for (int c = 0; c < NCHK; c++) {
        stage1_kernel<<<dim3(BCH / 64, NB1 / 4), 256, smem_s1>>>(x, c);
        stage2_kernel<<<dim3(BCH / 128, MMID), 256, smem_s2>>>((float*)d_out, c);
    }
}